// round 16
// baseline (speedup 1.0000x reference)
#include <cuda_runtime.h>
#include <cuda_fp16.h>
#include <math.h>
#include <stdint.h>

// ---------------------------------------------------------------------------
// Problem constants
// ---------------------------------------------------------------------------
#define BATCH   2
#define RES_H   32
#define RES_W   32
#define RES_L   16
#define WSZ     8
#define CDIM    384
#define NHEADS  12
#define HD      32
#define NTOK    (RES_H*RES_W*RES_L)       // 16384
#define BTROWS  (BATCH*NTOK)              // 32768
#define NWIN_B  ((RES_H/WSZ)*(RES_W/WSZ)*(RES_L/WSZ))  // 32
#define NWIN    (BATCH*NWIN_B)            // 64
#define WN      (WSZ*WSZ*WSZ)             // 512
#define KVGC    1152
#define HIDDEN  1536

// ---------------------------------------------------------------------------
// Scratch (static device globals)
// ---------------------------------------------------------------------------
static __device__ __align__(256) __half d_xw16[BTROWS*CDIM];
static __device__ __align__(256) __half d_yw16[BTROWS*CDIM];
static __device__ __align__(256) __half d_hn16[BTROWS*CDIM];
static __device__ __align__(256) __half d_xo16[BTROWS*CDIM];
static __device__ __align__(256) __half d_h116[BTROWS*HIDDEN];
static __device__ __align__(256) __half d_kvg16[BTROWS*KVGC];
static __device__ __align__(256) __half d_qb16[BTROWS*CDIM];
static __device__ __align__(256) __half d_wqh[1536*384];
static __device__ __align__(256) __half d_wph[384*384];
static __device__ __align__(256) __half d_w1h[1536*384];
static __device__ __align__(256) __half d_w2h[384*1536];

static __device__ float d_aw [BTROWS*CDIM];
static __device__ float d_x2 [BTROWS*CDIM];

// ---------------------------------------------------------------------------
// PTX helpers
// ---------------------------------------------------------------------------
__device__ __forceinline__ uint32_t smem_u32(const void* p) {
    uint32_t a;
    asm("{ .reg .u64 t; cvta.to.shared.u64 t, %1; cvt.u32.u64 %0, t; }"
        : "=r"(a) : "l"(p));
    return a;
}
__device__ __forceinline__ void cp_async16(uint32_t dst, const void* src) {
    asm volatile("cp.async.cg.shared.global [%0], [%1], 16;"
        :: "r"(dst), "l"(src) : "memory");
}
__device__ __forceinline__ void ldm4(uint32_t* r, uint32_t addr) {
    asm volatile("ldmatrix.sync.aligned.m8n8.x4.shared.b16 {%0,%1,%2,%3}, [%4];"
        : "=r"(r[0]), "=r"(r[1]), "=r"(r[2]), "=r"(r[3]) : "r"(addr));
}
__device__ __forceinline__ void mma16816(float* c, const uint32_t* a, const uint32_t* b) {
    asm volatile("mma.sync.aligned.m16n8k16.row.col.f32.f16.f16.f32 "
        "{%0,%1,%2,%3}, {%4,%5,%6,%7}, {%8,%9}, {%0,%1,%2,%3};"
        : "+f"(c[0]), "+f"(c[1]), "+f"(c[2]), "+f"(c[3])
        : "r"(a[0]), "r"(a[1]), "r"(a[2]), "r"(a[3]), "r"(b[0]), "r"(b[1]));
}

// ---------------------------------------------------------------------------
// misc helpers
// ---------------------------------------------------------------------------
__device__ __forceinline__ float warp_sum(float v) {
    #pragma unroll
    for (int o = 16; o; o >>= 1) v += __shfl_xor_sync(0xffffffffu, v, o);
    return v;
}
__device__ __forceinline__ int window_row(int bt) {
    int bb = bt >> 14;
    int t  = bt & 16383;
    int hh = t >> 9;
    int ww = (t >> 4) & 31;
    int ll = t & 15;
    int win = bb * NWIN_B + (((hh >> 3) * 4 + (ww >> 3)) * 2 + (ll >> 3));
    int n   = (((hh & 7) << 3) + (ww & 7)) * 8 + (ll & 7);
    return win * WN + n;
}
// fast x^p for x >= 0 (x==0 -> lg2 gives -inf -> ex2 gives 0)
__device__ __forceinline__ float fast_pow(float m, float p) {
    float lg, r;
    asm("lg2.approx.f32 %0, %1;" : "=f"(lg) : "f"(m));
    asm("ex2.approx.f32 %0, %1;" : "=f"(r) : "f"(p * lg));
    return r;
}

// ---------------------------------------------------------------------------
// all weights: fp32 -> fp16, single launch
// ---------------------------------------------------------------------------
__global__ void __launch_bounds__(256) cvt_all_kernel(
    const float4* __restrict__ s0, uint2* __restrict__ h0, int n0,
    const float4* __restrict__ s1, uint2* __restrict__ h1, int n1,
    const float4* __restrict__ s2, uint2* __restrict__ h2, int n2,
    const float4* __restrict__ s3, uint2* __restrict__ h3, int n3)
{
    int i = blockIdx.x * blockDim.x + threadIdx.x;
    const float4* s; uint2* hp; int idx;
    if (i < n0)                { s = s0; hp = h0; idx = i; }
    else if (i < n0+n1)        { s = s1; hp = h1; idx = i - n0; }
    else if (i < n0+n1+n2)     { s = s2; hp = h2; idx = i - n0 - n1; }
    else if (i < n0+n1+n2+n3)  { s = s3; hp = h3; idx = i - n0 - n1 - n2; }
    else return;
    float4 v = s[idx];
    __half2 ph0 = __halves2half2(__float2half(v.x), __float2half(v.y));
    __half2 ph1 = __halves2half2(__float2half(v.z), __float2half(v.w));
    uint2 uh; uh.x = *(uint32_t*)&ph0; uh.y = *(uint32_t*)&ph1;
    hp[idx] = uh;
}

// ---------------------------------------------------------------------------
// LayerNorm fused with window partition -> fp16; y selects (x->xw | y->yw)
// ---------------------------------------------------------------------------
__global__ void __launch_bounds__(256) ln_win_kernel(
    const float* __restrict__ xa, const float* __restrict__ xb,
    const float* __restrict__ g, const float* __restrict__ b,
    __half* __restrict__ oa, __half* __restrict__ ob)
{
    int warp = (blockIdx.x * blockDim.x + threadIdx.x) >> 5;
    int lane = threadIdx.x & 31;
    if (warp >= BTROWS) return;
    const float* x = blockIdx.y ? xb : xa;
    __half* o16 = blockIdx.y ? ob : oa;
    const float* xr = x + (size_t)warp * CDIM;
    float v[12];
    float s = 0.f;
    #pragma unroll
    for (int i = 0; i < 12; i++) { v[i] = xr[lane + i * 32]; s += v[i]; }
    s = warp_sum(s);
    float mu = s * (1.f / 384.f);
    float sq = 0.f;
    #pragma unroll
    for (int i = 0; i < 12; i++) { float dv = v[i] - mu; sq += dv * dv; }
    sq = warp_sum(sq);
    float rstd = rsqrtf(sq * (1.f / 384.f) + 1e-5f);
    size_t ro = (size_t)window_row(warp) * CDIM;
    #pragma unroll
    for (int i = 0; i < 12; i++) {
        int c = lane + i * 32;
        float o = (v[i] - mu) * rstd * g[c] + b[c];
        o16[ro + c] = __float2half(o);
    }
}

// ---------------------------------------------------------------------------
// residual-add (window_reverse) + LN2 -> x2 fp32, hn fp16
// ---------------------------------------------------------------------------
__global__ void __launch_bounds__(256) resln_kernel(
    const float* __restrict__ x, const float* __restrict__ aw,
    const float* __restrict__ g, const float* __restrict__ b,
    float* __restrict__ x2, __half* __restrict__ hn)
{
    int warp = (blockIdx.x * blockDim.x + threadIdx.x) >> 5;
    int lane = threadIdx.x & 31;
    if (warp >= BTROWS) return;
    const float* xr = x  + (size_t)warp * CDIM;
    const float* ar = aw + (size_t)window_row(warp) * CDIM;
    float v[12];
    float s = 0.f;
    #pragma unroll
    for (int i = 0; i < 12; i++) {
        int c = lane + i * 32;
        v[i] = xr[c] + ar[c];
        s += v[i];
    }
    s = warp_sum(s);
    float mu = s * (1.f / 384.f);
    float sq = 0.f;
    #pragma unroll
    for (int i = 0; i < 12; i++) { float dv = v[i] - mu; sq += dv * dv; }
    sq = warp_sum(sq);
    float rstd = rsqrtf(sq * (1.f / 384.f) + 1e-5f);
    size_t ro = (size_t)warp * CDIM;
    #pragma unroll
    for (int i = 0; i < 12; i++) {
        int c = lane + i * 32;
        x2[ro + c] = v[i];
        float o = (v[i] - mu) * rstd * g[c] + b[c];
        hn[ro + c] = __float2half(o);
    }
}

// ---------------------------------------------------------------------------
// mma.sync GEMM body (single fp16 pass)
// ---------------------------------------------------------------------------
#define GSTAGE 16384
#define GSMEM_BYTES (4*GSTAGE)

template <int EPI>
__device__ __forceinline__ void gemm_body(
    const __half* __restrict__ A, const __half* __restrict__ Bh,
    const float* __restrict__ bias, const float* __restrict__ res,
    float* __restrict__ C, __half* __restrict__ C16,
    int N, int K, int bm, int bn, char* smem)
{
    const uint32_t sbase = smem_u32(smem);
    const int tid  = threadIdx.x;
    const int lane = tid & 31;
    const int wid  = tid >> 5;
    const int wm   = wid & 1;
    const int wn   = wid >> 1;

    float acc[4][4][4];
    #pragma unroll
    for (int i = 0; i < 4; i++)
        #pragma unroll
        for (int j = 0; j < 4; j++)
            #pragma unroll
            for (int q = 0; q < 4; q++) acc[i][j][q] = 0.f;

    #define LOAD_STAGE(stage, k0) do {                                        \
        uint32_t sb_ = sbase + (uint32_t)(stage) * GSTAGE;                    \
        const __half* bases_[2] = {A, Bh};                                    \
        _Pragma("unroll")                                                     \
        for (int sub_ = 0; sub_ < 2; sub_++) {                                \
            const __half* bp_ = bases_[sub_];                                 \
            int ro_ = (sub_ == 0) ? bm : bn;                                  \
            _Pragma("unroll")                                                 \
            for (int jj_ = 0; jj_ < 2; jj_++) {                               \
                int cid_ = tid + 256 * jj_;                                   \
                int row_ = cid_ >> 2, ck_ = cid_ & 3;                         \
                int cs_ = ck_ ^ ((row_ >> 1) & 3);                            \
                const void* src_ = bp_ + (size_t)(ro_ + row_) * K + (k0) + ck_ * 8; \
                cp_async16(sb_ + (uint32_t)(sub_ << 13)                       \
                           + (uint32_t)(row_ * 64 + cs_ * 16), src_);         \
            }                                                                 \
        }                                                                     \
    } while (0)

    const int NC = K >> 5;
    LOAD_STAGE(0, 0);
    asm volatile("cp.async.commit_group;" ::: "memory");
    LOAD_STAGE(1, 32);
    asm volatile("cp.async.commit_group;" ::: "memory");
    LOAD_STAGE(2, 64);
    asm volatile("cp.async.commit_group;" ::: "memory");

    const int arow = wm * 64 + (lane & 15);
    const int asel = lane >> 4;
    const int brow = wn * 32 + ((lane >> 4) << 3) + (lane & 7);
    const int bsel = (lane >> 3) & 1;

    for (int c = 0; c < NC; c++) {
        asm volatile("cp.async.wait_group 2;" ::: "memory");
        __syncthreads();
        if (c + 3 < NC) {
            LOAD_STAGE((c + 3) & 3, (c + 3) << 5);
            asm volatile("cp.async.commit_group;" ::: "memory");
        }

        const uint32_t sb = sbase + (uint32_t)(c & 3) * GSTAGE;
        #pragma unroll
        for (int kk = 0; kk < 2; kk++) {
            uint32_t a[4][4], bh[2][4];
            #pragma unroll
            for (int mt = 0; mt < 4; mt++) {
                int row = arow + mt * 16;
                int ck  = kk * 2 + asel;
                uint32_t off = (uint32_t)(row * 64 + (ck ^ ((row >> 1) & 3)) * 16);
                ldm4(a[mt], sb + off);
            }
            #pragma unroll
            for (int bt = 0; bt < 2; bt++) {
                int row = brow + bt * 16;
                int ck  = kk * 2 + bsel;
                uint32_t off = (uint32_t)(row * 64 + (ck ^ ((row >> 1) & 3)) * 16);
                ldm4(bh[bt], sb + 8192u + off);
            }
            #pragma unroll
            for (int mt = 0; mt < 4; mt++) {
                #pragma unroll
                for (int nt = 0; nt < 4; nt++) {
                    const uint32_t* bhf = &bh[nt >> 1][(nt & 1) * 2];
                    mma16816(acc[mt][nt], a[mt], bhf);
                }
            }
        }
    }

    // ---- epilogue ----
    const int gr = lane >> 2;
    const int nc0 = (lane & 3) * 2;
    #pragma unroll
    for (int mt = 0; mt < 4; mt++) {
        #pragma unroll
        for (int nt = 0; nt < 4; nt++) {
            int col = bn + wn * 32 + nt * 8 + nc0;
            float bs0 = bias[col], bs1 = bias[col + 1];
            #pragma unroll
            for (int half = 0; half < 2; half++) {
                int row = bm + wm * 64 + mt * 16 + gr + half * 8;
                float v0 = acc[mt][nt][half * 2 + 0] + bs0;
                float v1 = acc[mt][nt][half * 2 + 1] + bs1;
                size_t off = (size_t)row * N + col;
                if (EPI == 1 || EPI == 3) {
                    if (EPI == 1) {
                        v0 = 0.5f * v0 * (1.f + erff(v0 * 0.70710678118654752f));
                        v1 = 0.5f * v1 * (1.f + erff(v1 * 0.70710678118654752f));
                    }
                    __half2 p = __halves2half2(__float2half(v0), __float2half(v1));
                    *(uint32_t*)(C16 + off) = *(uint32_t*)&p;
                } else {
                    if (EPI == 2) { v0 += res[off]; v1 += res[off + 1]; }
                    float2 o; o.x = v0; o.y = v1;
                    *(float2*)(C + off) = o;
                }
            }
        }
    }
    #undef LOAD_STAGE
}

template <int EPI>
__global__ void __launch_bounds__(256, 2) mma_gemm(
    const __half* __restrict__ A, const __half* __restrict__ Bh,
    const float* __restrict__ bias, const float* __restrict__ res,
    float* __restrict__ C, __half* __restrict__ C16, int N, int K)
{
    extern __shared__ char smem[];
    gemm_body<EPI>(A, Bh, bias, res, C, C16, N, K,
                   blockIdx.y * 128, blockIdx.x * 128, smem);
}

// fused kvg + q GEMM: blockIdx.x < 9 -> kvg tile, else q tile
__global__ void __launch_bounds__(256, 2) mma_gemm_qkv(
    const __half* __restrict__ xw, const __half* __restrict__ yw,
    const __half* __restrict__ wq, const float* __restrict__ bq,
    __half* __restrict__ kvg16, __half* __restrict__ qb16)
{
    extern __shared__ char smem[];
    if (blockIdx.x < 9) {
        gemm_body<3>(xw, wq + 384*384, bq + 384, nullptr, nullptr, kvg16,
                     KVGC, 384, blockIdx.y * 128, blockIdx.x * 128, smem);
    } else {
        gemm_body<3>(yw, wq, bq, nullptr, nullptr, qb16,
                     CDIM, 384, blockIdx.y * 128, (blockIdx.x - 9) * 128, smem);
    }
}

// ---------------------------------------------------------------------------
// Pola linear attention, one block per (window, head). 256 threads.
// 128-token chunks; d-quad loaders; float4 ksum partials (aliased into buf);
// z folded. __launch_bounds__(256,4) for 4 CTAs/SM (64-reg cap).
// Dynamic smem (floats): sc[32] pw[32] km2[2][64] buf[128][68] vS[128][36]
// ---------------------------------------------------------------------------
#define ATTN_SMEM ((32 + 32 + 128 + 128*68 + 128*36) * 4)

__global__ void __launch_bounds__(256, 4) attn_kernel(
    const __half* __restrict__ kvg, const __half* __restrict__ qb,
    const float* __restrict__ pos_enc, const float* __restrict__ scale_p,
    const float* __restrict__ power_p, __half* __restrict__ xo)
{
    extern __shared__ float asmem[];
    float* sc_s  = asmem;            // [32]
    float* pw_s  = asmem + 32;       // [32]
    float* km2_s = asmem + 64;       // [2][64]
    float (*buf)[68] = (float(*)[68])(asmem + 192);
    float (*vS)[36]  = (float(*)[36])(asmem + 192 + 128*68);
    float* ks16  = asmem + 192;      // [16][64] alias of buf (free between phases)

    const int wg = blockIdx.x;   // 0..63
    const int h  = blockIdx.y;   // 0..11
    const int tid = threadIdx.x;

    if (tid < 32) {
        float sp = scale_p[h * 32 + tid];
        sc_s[tid] = 1.f / log1pf(expf(sp));          // 1/softplus
        float pp = power_p[h * 32 + tid];
        pw_s[tid] = 1.f + 4.f / (1.f + expf(-pp));   // 1 + ALPHA*sigmoid
    }
    __syncthreads();

    const int nh = tid >> 7;
    const int tt = tid & 127;
    const int fq = (tt >> 3) << 2;
    const int dq = (tt & 7) << 2;
    const int kfg = (tid & 15) << 2;  // ksum feature quad base
    const int krg = tid >> 4;         // ksum row group (0..15), 8 rows each

    float acc[4][4];
    #pragma unroll
    for (int i = 0; i < 4; i++)
        #pragma unroll
        for (int j = 0; j < 4; j++) acc[i][j] = 0.f;
    float ks0 = 0.f, ks1 = 0.f, ks2 = 0.f, ks3 = 0.f;

    // -------- phase A: kc features (d-quad loader), kv = kc^T v, ksum -------
    for (int c0 = 0; c0 < WN; c0 += 128) {
        #pragma unroll
        for (int i = 0; i < 4; i++) {
            int idx = tid + 256 * i;      // 0..1023
            int nl = idx >> 3;            // 0..127
            int d0 = (idx & 7) << 2;      // 0,4,..,28
            int row = wg * WN + c0 + nl;
            uint2 ku = *(const uint2*)&kvg[(size_t)row * KVGC + h * 32 + d0];
            float2 ka = __half22float2(*(__half2*)&ku.x);
            float2 kb = __half22float2(*(__half2*)&ku.y);
            float4 pe = *(const float4*)&pos_enc[(c0 + nl) * CDIM + h * 32 + d0];
            float kv0 = (ka.x + pe.x) * sc_s[d0];
            float kv1 = (ka.y + pe.y) * sc_s[d0 + 1];
            float kv2 = (kb.x + pe.z) * sc_s[d0 + 2];
            float kv3 = (kb.y + pe.w) * sc_s[d0 + 3];
            float r0 = fast_pow(fabsf(kv0), pw_s[d0]);
            float r1 = fast_pow(fabsf(kv1), pw_s[d0 + 1]);
            float r2 = fast_pow(fabsf(kv2), pw_s[d0 + 2]);
            float r3 = fast_pow(fabsf(kv3), pw_s[d0 + 3]);
            float4 pv, nv;
            pv.x = kv0 > 0.f ? r0 : 0.f; nv.x = kv0 < 0.f ? r0 : 0.f;
            pv.y = kv1 > 0.f ? r1 : 0.f; nv.y = kv1 < 0.f ? r1 : 0.f;
            pv.z = kv2 > 0.f ? r2 : 0.f; nv.z = kv2 < 0.f ? r2 : 0.f;
            pv.w = kv3 > 0.f ? r3 : 0.f; nv.w = kv3 < 0.f ? r3 : 0.f;
            *(float4*)&buf[nl][d0]      = pv;
            *(float4*)&buf[nl][d0 + 32] = nv;
            uint2 vu = *(const uint2*)&kvg[(size_t)row * KVGC + 384 + h * 32 + d0];
            float2 va = __half22float2(*(__half2*)&vu.x);
            float2 vb = __half22float2(*(__half2*)&vu.y);
            float4 vf; vf.x = va.x; vf.y = va.y; vf.z = vb.x; vf.w = vb.y;
            *(float4*)&vS[nl][d0] = vf;
        }
        __syncthreads();
        #pragma unroll 4
        for (int n = 0; n < 64; n++) {
            int nn = (nh << 6) + n;
            float4 kq = *(const float4*)&buf[nn][fq];
            float4 v4 = *(const float4*)&vS[nn][dq];
            acc[0][0] += kq.x * v4.x; acc[0][1] += kq.x * v4.y;
            acc[0][2] += kq.x * v4.z; acc[0][3] += kq.x * v4.w;
            acc[1][0] += kq.y * v4.x; acc[1][1] += kq.y * v4.y;
            acc[1][2] += kq.y * v4.z; acc[1][3] += kq.y * v4.w;
            acc[2][0] += kq.z * v4.x; acc[2][1] += kq.z * v4.y;
            acc[2][2] += kq.z * v4.z; acc[2][3] += kq.z * v4.w;
            acc[3][0] += kq.w * v4.x; acc[3][1] += kq.w * v4.y;
            acc[3][2] += kq.w * v4.z; acc[3][3] += kq.w * v4.w;
        }
        // ksum partial: 8 rows x feature-quad per thread, float4 loads
        #pragma unroll
        for (int n = 0; n < 8; n++) {
            float4 kq = *(const float4*)&buf[krg * 8 + n][kfg];
            ks0 += kq.x; ks1 += kq.y; ks2 += kq.z; ks3 += kq.w;
        }
        __syncthreads();
    }

    // -------- merge n-halves + ksum partials, write M and km vectors --------
    // ks16 aliases buf: safe — all buf reads of phase A are complete.
    float4 ksq; ksq.x = ks0; ksq.y = ks1; ksq.z = ks2; ksq.w = ks3;
    *(float4*)&ks16[krg * 64 + kfg] = ksq;
    if (nh == 1) {
        #pragma unroll
        for (int i = 0; i < 4; i++)
            #pragma unroll
            for (int j = 0; j < 4; j++)
                vS[fq + i][dq + j] = acc[i][j];
    }
    __syncthreads();
    float mreg[4][4];
    if (nh == 0) {
        const float sN2 = 1.f / 512.f;
        #pragma unroll
        for (int i = 0; i < 4; i++)
            #pragma unroll
            for (int j = 0; j < 4; j++)
                mreg[i][j] = (acc[i][j] + vS[fq + i][dq + j]) * sN2;
    }
    if (tid < 64) {
        float km = 0.f;
        #pragma unroll
        for (int r = 0; r < 16; r++) km += ks16[r * 64 + tid];
        km *= (1.f / 512.f);
        km2_s[tid] = km;
        km2_s[64 + ((tid + 32) & 63)] = km;
    }
    __syncthreads();
    if (nh == 0) {
        #pragma unroll
        for (int i = 0; i < 4; i++) {
            int fr = (dq < 16) ? (fq + i) : ((fq + i + 32) & 63);
            #pragma unroll
            for (int j = 0; j < 4; j++)
                vS[fr][dq + j] = mreg[i][j];
        }
    }
    __syncthreads();

    // -------- phase C: q features (d-quad loader) + O = qf @ M + z, write ---
    const int n0 = (tid >> 3) << 2;   // 0,4,..,124
    const int vc = (tid & 7) << 2;    // 0,4,..,28
    const int zi = (vc >= 16) ? 1 : 0;
    const float* kmz = km2_s + zi * 64;
    for (int c0 = 0; c0 < WN; c0 += 128) {
        #pragma unroll
        for (int i = 0; i < 4; i++) {
            int idx = tid + 256 * i;
            int nl = idx >> 3;
            int d0 = (idx & 7) << 2;
            int row = wg * WN + c0 + nl;
            uint2 qu = *(const uint2*)&qb[(size_t)row * CDIM + h * 32 + d0];
            float2 qa = __half22float2(*(__half2*)&qu.x);
            float2 qc = __half22float2(*(__half2*)&qu.y);
            float qv0 = qa.x * sc_s[d0];
            float qv1 = qa.y * sc_s[d0 + 1];
            float qv2 = qc.x * sc_s[d0 + 2];
            float qv3 = qc.y * sc_s[d0 + 3];
            float r0 = fast_pow(fabsf(qv0), pw_s[d0]);
            float r1 = fast_pow(fabsf(qv1), pw_s[d0 + 1]);
            float r2 = fast_pow(fabsf(qv2), pw_s[d0 + 2]);
            float r3 = fast_pow(fabsf(qv3), pw_s[d0 + 3]);
            float4 pv, nv;
            pv.x = qv0 > 0.f ? r0 : 0.f; nv.x = qv0 < 0.f ? r0 : 0.f;
            pv.y = qv1 > 0.f ? r1 : 0.f; nv.y = qv1 < 0.f ? r1 : 0.f;
            pv.z = qv2 > 0.f ? r2 : 0.f; nv.z = qv2 < 0.f ? r2 : 0.f;
            pv.w = qv3 > 0.f ? r3 : 0.f; nv.w = qv3 < 0.f ? r3 : 0.f;
            *(float4*)&buf[nl][d0]      = pv;
            *(float4*)&buf[nl][d0 + 32] = nv;
        }
        __syncthreads();

        float a[4][4];
        float z[4];
        #pragma unroll
        for (int t = 0; t < 4; t++) {
            z[t] = 1e-6f;
            #pragma unroll
            for (int j = 0; j < 4; j++) a[t][j] = 0.f;
        }
        #pragma unroll 2
        for (int f = 0; f < 64; f += 4) {
            float4 m0 = *(const float4*)&vS[f + 0][vc];
            float4 m1 = *(const float4*)&vS[f + 1][vc];
            float4 m2 = *(const float4*)&vS[f + 2][vc];
            float4 m3 = *(const float4*)&vS[f + 3][vc];
            float4 kv = *(const float4*)&kmz[f];
            #pragma unroll
            for (int t = 0; t < 4; t++) {
                float4 q = *(const float4*)&buf[n0 + t][f];
                a[t][0] += q.x * m0.x + q.y * m1.x + q.z * m2.x + q.w * m3.x;
                a[t][1] += q.x * m0.y + q.y * m1.y + q.z * m2.y + q.w * m3.y;
                a[t][2] += q.x * m0.z + q.y * m1.z + q.z * m2.z + q.w * m3.z;
                a[t][3] += q.x * m0.w + q.y * m1.w + q.z * m2.w + q.w * m3.w;
                z[t]    += q.x * kv.x + q.y * kv.y + q.z * kv.z + q.w * kv.w;
            }
        }

        size_t base0 = (size_t)(wg * WN + c0 + n0) * CDIM + h * 32 + vc;
        #pragma unroll
        for (int t = 0; t < 4; t++) {
            float rz = 1.f / z[t];
            __half2 p0 = __halves2half2(__float2half(a[t][0] * rz),
                                        __float2half(a[t][1] * rz));
            __half2 p1 = __halves2half2(__float2half(a[t][2] * rz),
                                        __float2half(a[t][3] * rz));
            uint2 o; o.x = *(uint32_t*)&p0; o.y = *(uint32_t*)&p1;
            *(uint2*)&xo[base0 + (size_t)t * CDIM] = o;
        }
        __syncthreads();
    }
}

// ---------------------------------------------------------------------------
// Depthwise 5^3 conv + (xo + vv) * g, in place on fp16 xo plane.
// Round-9 form: scalar fp32 smem, thread owns one d; 16-output register tile.
// ---------------------------------------------------------------------------
#define CONV_SMEM ((512*32 + 125*32) * 4)

__global__ void __launch_bounds__(256) dwconv_kernel(
    const __half* __restrict__ kvg, const float* __restrict__ dwc_w,
    const float* __restrict__ dwc_b, __half* __restrict__ xo16)
{
    extern __shared__ float sm[];
    float* v_s = sm;               // [512][32] fp32
    float* w_s = sm + 512 * 32;    // [125][32] fp32
    const int bh = blockIdx.x;
    const int b_ = bh / NHEADS, h = bh % NHEADS;
    const int tid = threadIdx.x;

    for (int i = tid; i < 512 * 32; i += 256) {
        int n = i >> 5, d = i & 31;
        v_s[i] = __half2float(kvg[(size_t)(b_ * WN + n) * KVGC + 384 + h * 32 + d]);
    }
    for (int i = tid; i < 125 * 32; i += 256) w_s[i] = dwc_w[i];
    __syncthreads();

    const int d  = tid & 31;
    const int lo = tid >> 5;
    const float bval = dwc_b[d];
    const size_t base = (size_t)b_ * (WN * CDIM) + (size_t)h * (WN * HD);

    for (int jg = 0; jg < 4; jg++) {
        float acc[16];
        #pragma unroll
        for (int jj = 0; jj < 16; jj++) acc[jj] = bval;
        for (int kd = 0; kd < 5; kd++) {
            for (int kh = 0; kh < 5; kh++) {
                for (int kw = 0; kw < 5; kw++) {
                    int li = lo + kw - 2;
                    if (li < 0 || li > 7) continue;
                    float w = w_s[((kd * 5 + kh) * 5 + kw) * 32 + d];
                    #pragma unroll
                    for (int jj = 0; jj < 16; jj++) {
                        int j = jg * 16 + jj;
                        int hi = (j >> 3) + kd - 2;
                        int wi = (j & 7) + kh - 2;
                        if (hi < 0 || hi > 7 || wi < 0 || wi > 7) continue;
                        acc[jj] += v_s[((hi * 8 + wi) * 8 + li) * 32 + d] * w;
                    }
                }
            }
        }
        #pragma unroll
        for (int jj = 0; jj < 16; jj++) {
            int j = jg * 16 + jj;
            size_t flat = base + (size_t)(lo + 8 * j) * 32 + d;
            size_t grow = flat / CDIM;
            int    gcol = (int)(flat % CDIM);
            float g = __half2float(kvg[grow * KVGC + 768 + gcol]);
            float val = (__half2float(xo16[flat]) + acc[jj]) * g;
            xo16[flat] = __float2half(val);
        }
    }
}

// ---------------------------------------------------------------------------
// kernel_launch
// ---------------------------------------------------------------------------
extern "C" void kernel_launch(void* const* d_in, const int* in_sizes, int n_in,
                              void* d_out, int out_size)
{
    const float* x       = (const float*)d_in[0];
    const float* y       = (const float*)d_in[1];
    const float* w_qkvg  = (const float*)d_in[2];
    const float* b_qkvg  = (const float*)d_in[3];
    const float* w_proj  = (const float*)d_in[4];
    const float* b_proj  = (const float*)d_in[5];
    const float* dwc_w   = (const float*)d_in[6];
    const float* dwc_b   = (const float*)d_in[7];
    const float* power_p = (const float*)d_in[8];
    const float* scale_p = (const float*)d_in[9];
    const float* pos_enc = (const float*)d_in[10];
    const float* g1      = (const float*)d_in[11];
    const float* b1      = (const float*)d_in[12];
    const float* g2      = (const float*)d_in[13];
    const float* b2      = (const float*)d_in[14];
    const float* w_fc1   = (const float*)d_in[15];
    const float* b_fc1   = (const float*)d_in[16];
    const float* w_fc2   = (const float*)d_in[17];
    const float* b_fc2   = (const float*)d_in[18];
    float* out = (float*)d_out;

    __half *p_xw16, *p_yw16, *p_hn16, *p_xo16, *p_h116, *p_kvg16, *p_qb16;
    __half *p_wqh, *p_wph, *p_w1h, *p_w2h;
    float *p_aw, *p_x2;
    cudaGetSymbolAddress((void**)&p_xw16, d_xw16);
    cudaGetSymbolAddress((void**)&p_yw16, d_yw16);
    cudaGetSymbolAddress((void**)&p_hn16, d_hn16);
    cudaGetSymbolAddress((void**)&p_xo16, d_xo16);
    cudaGetSymbolAddress((void**)&p_h116, d_h116);
    cudaGetSymbolAddress((void**)&p_kvg16, d_kvg16);
    cudaGetSymbolAddress((void**)&p_qb16, d_qb16);
    cudaGetSymbolAddress((void**)&p_wqh, d_wqh);
    cudaGetSymbolAddress((void**)&p_wph, d_wph);
    cudaGetSymbolAddress((void**)&p_w1h, d_w1h);
    cudaGetSymbolAddress((void**)&p_w2h, d_w2h);
    cudaGetSymbolAddress((void**)&p_aw,  d_aw);
    cudaGetSymbolAddress((void**)&p_x2,  d_x2);

    cudaFuncSetAttribute(dwconv_kernel,
                         cudaFuncAttributeMaxDynamicSharedMemorySize, CONV_SMEM);
    cudaFuncSetAttribute(attn_kernel,
                         cudaFuncAttributeMaxDynamicSharedMemorySize, ATTN_SMEM);
    cudaFuncSetAttribute(mma_gemm<0>,
                         cudaFuncAttributeMaxDynamicSharedMemorySize, GSMEM_BYTES);
    cudaFuncSetAttribute(mma_gemm<1>,
                         cudaFuncAttributeMaxDynamicSharedMemorySize, GSMEM_BYTES);
    cudaFuncSetAttribute(mma_gemm<2>,
                         cudaFuncAttributeMaxDynamicSharedMemorySize, GSMEM_BYTES);
    cudaFuncSetAttribute(mma_gemm_qkv,
                         cudaFuncAttributeMaxDynamicSharedMemorySize, GSMEM_BYTES);

    // 0) weight -> fp16, single launch
    {
        int n0 = 1536*384/4, n1 = 384*384/4, n2 = 1536*384/4, n3 = 384*1536/4;
        int tot = n0 + n1 + n2 + n3;
        cvt_all_kernel<<<(tot + 255)/256, 256>>>(
            (const float4*)w_qkvg, (uint2*)p_wqh, n0,
            (const float4*)w_proj, (uint2*)p_wph, n1,
            (const float4*)w_fc1,  (uint2*)p_w1h, n2,
            (const float4*)w_fc2,  (uint2*)p_w2h, n3);
    }

    // 1) LN + window partition (x and y in one launch) -> fp16
    ln_win_kernel<<<dim3(BTROWS / 8, 2), 256>>>(x, y, g1, b1, p_xw16, p_yw16);

    // 2+3) fused kvg + q GEMM (single pass) -> fp16
    mma_gemm_qkv<<<dim3(12, BTROWS/128), 256, GSMEM_BYTES>>>(
        p_xw16, p_yw16, p_wqh, b_qkvg, p_kvg16, p_qb16);

    // 4) attention -> xo16
    attn_kernel<<<dim3(NWIN, NHEADS), 256, ATTN_SMEM>>>(
        p_kvg16, p_qb16, pos_enc, scale_p, power_p, p_xo16);

    // 5) depthwise conv + gating, in place on xo16
    dwconv_kernel<<<NWIN * NHEADS, 256, CONV_SMEM>>>(p_kvg16, dwc_w, dwc_b,
                                                     p_xo16);

    // 6) aw = xo @ w_proj^T + b_proj -> fp32 (single pass)
    mma_gemm<0><<<dim3(CDIM/128, BTROWS/128), 256, GSMEM_BYTES>>>(
        p_xo16, p_wph, b_proj, nullptr, p_aw, nullptr, CDIM, 384);

    // 7) x2 = x + window_reverse(aw); hn = LN2(x2) -> fp16
    resln_kernel<<<BTROWS / 8, 256>>>(x, p_aw, g2, b2, p_x2, p_hn16);

    // 8) h1 = gelu(hn @ w_fc1^T + b_fc1) -> fp16 (single pass, N=1536)
    mma_gemm<1><<<dim3(HIDDEN/128, BTROWS/128), 256, GSMEM_BYTES>>>(
        p_hn16, p_w1h, b_fc1, nullptr, nullptr, p_h116, HIDDEN, 384);

    // 9) out = x2 + h1 @ w_fc2^T + b_fc2 (single pass, K=1536)
    mma_gemm<2><<<dim3(CDIM/128, BTROWS/128), 256, GSMEM_BYTES>>>(
        p_h116, p_w2h, b_fc2, p_x2, out, nullptr, CDIM, 1536);
}

// round 17
// speedup vs baseline: 1.0451x; 1.0451x over previous
#include <cuda_runtime.h>
#include <cuda_fp16.h>
#include <math.h>
#include <stdint.h>

// ---------------------------------------------------------------------------
// Problem constants
// ---------------------------------------------------------------------------
#define BATCH   2
#define RES_H   32
#define RES_W   32
#define RES_L   16
#define WSZ     8
#define CDIM    384
#define NHEADS  12
#define HD      32
#define NTOK    (RES_H*RES_W*RES_L)       // 16384
#define BTROWS  (BATCH*NTOK)              // 32768
#define NWIN_B  ((RES_H/WSZ)*(RES_W/WSZ)*(RES_L/WSZ))  // 32
#define NWIN    (BATCH*NWIN_B)            // 64
#define WN      (WSZ*WSZ*WSZ)             // 512
#define KVGC    1152
#define HIDDEN  1536

// ---------------------------------------------------------------------------
// Scratch (static device globals)
// ---------------------------------------------------------------------------
static __device__ __align__(256) __half d_xw16[BTROWS*CDIM];
static __device__ __align__(256) __half d_yw16[BTROWS*CDIM];
static __device__ __align__(256) __half d_hn16[BTROWS*CDIM];
static __device__ __align__(256) __half d_xo16[BTROWS*CDIM];
static __device__ __align__(256) __half d_h116[BTROWS*HIDDEN];
static __device__ __align__(256) __half d_kvg16[BTROWS*KVGC];
static __device__ __align__(256) __half d_qb16[BTROWS*CDIM];
static __device__ __align__(256) __half d_wqh[1536*384];
static __device__ __align__(256) __half d_wph[384*384];
static __device__ __align__(256) __half d_w1h[1536*384];
static __device__ __align__(256) __half d_w2h[384*1536];

static __device__ float d_aw [BTROWS*CDIM];
static __device__ float d_x2 [BTROWS*CDIM];

// ---------------------------------------------------------------------------
// PTX helpers
// ---------------------------------------------------------------------------
__device__ __forceinline__ uint32_t smem_u32(const void* p) {
    uint32_t a;
    asm("{ .reg .u64 t; cvta.to.shared.u64 t, %1; cvt.u32.u64 %0, t; }"
        : "=r"(a) : "l"(p));
    return a;
}
__device__ __forceinline__ void cp_async16(uint32_t dst, const void* src) {
    asm volatile("cp.async.cg.shared.global [%0], [%1], 16;"
        :: "r"(dst), "l"(src) : "memory");
}
__device__ __forceinline__ void ldm4(uint32_t* r, uint32_t addr) {
    asm volatile("ldmatrix.sync.aligned.m8n8.x4.shared.b16 {%0,%1,%2,%3}, [%4];"
        : "=r"(r[0]), "=r"(r[1]), "=r"(r[2]), "=r"(r[3]) : "r"(addr));
}
__device__ __forceinline__ void mma16816(float* c, const uint32_t* a, const uint32_t* b) {
    asm volatile("mma.sync.aligned.m16n8k16.row.col.f32.f16.f16.f32 "
        "{%0,%1,%2,%3}, {%4,%5,%6,%7}, {%8,%9}, {%0,%1,%2,%3};"
        : "+f"(c[0]), "+f"(c[1]), "+f"(c[2]), "+f"(c[3])
        : "r"(a[0]), "r"(a[1]), "r"(a[2]), "r"(a[3]), "r"(b[0]), "r"(b[1]));
}

// ---------------------------------------------------------------------------
// misc helpers
// ---------------------------------------------------------------------------
__device__ __forceinline__ float warp_sum(float v) {
    #pragma unroll
    for (int o = 16; o; o >>= 1) v += __shfl_xor_sync(0xffffffffu, v, o);
    return v;
}
__device__ __forceinline__ int window_row(int bt) {
    int bb = bt >> 14;
    int t  = bt & 16383;
    int hh = t >> 9;
    int ww = (t >> 4) & 31;
    int ll = t & 15;
    int win = bb * NWIN_B + (((hh >> 3) * 4 + (ww >> 3)) * 2 + (ll >> 3));
    int n   = (((hh & 7) << 3) + (ww & 7)) * 8 + (ll & 7);
    return win * WN + n;
}
// fast x^p for x >= 0 (x==0 -> lg2 gives -inf -> ex2 gives 0)
__device__ __forceinline__ float fast_pow(float m, float p) {
    float lg, r;
    asm("lg2.approx.f32 %0, %1;" : "=f"(lg) : "f"(m));
    asm("ex2.approx.f32 %0, %1;" : "=f"(r) : "f"(p * lg));
    return r;
}

// ---------------------------------------------------------------------------
// all weights: fp32 -> fp16, single launch
// ---------------------------------------------------------------------------
__global__ void __launch_bounds__(256) cvt_all_kernel(
    const float4* __restrict__ s0, uint2* __restrict__ h0, int n0,
    const float4* __restrict__ s1, uint2* __restrict__ h1, int n1,
    const float4* __restrict__ s2, uint2* __restrict__ h2, int n2,
    const float4* __restrict__ s3, uint2* __restrict__ h3, int n3)
{
    int i = blockIdx.x * blockDim.x + threadIdx.x;
    const float4* s; uint2* hp; int idx;
    if (i < n0)                { s = s0; hp = h0; idx = i; }
    else if (i < n0+n1)        { s = s1; hp = h1; idx = i - n0; }
    else if (i < n0+n1+n2)     { s = s2; hp = h2; idx = i - n0 - n1; }
    else if (i < n0+n1+n2+n3)  { s = s3; hp = h3; idx = i - n0 - n1 - n2; }
    else return;
    float4 v = s[idx];
    __half2 ph0 = __halves2half2(__float2half(v.x), __float2half(v.y));
    __half2 ph1 = __halves2half2(__float2half(v.z), __float2half(v.w));
    uint2 uh; uh.x = *(uint32_t*)&ph0; uh.y = *(uint32_t*)&ph1;
    hp[idx] = uh;
}

// ---------------------------------------------------------------------------
// LayerNorm fused with window partition -> fp16; y selects (x->xw | y->yw)
// ---------------------------------------------------------------------------
__global__ void __launch_bounds__(256) ln_win_kernel(
    const float* __restrict__ xa, const float* __restrict__ xb,
    const float* __restrict__ g, const float* __restrict__ b,
    __half* __restrict__ oa, __half* __restrict__ ob)
{
    int warp = (blockIdx.x * blockDim.x + threadIdx.x) >> 5;
    int lane = threadIdx.x & 31;
    if (warp >= BTROWS) return;
    const float* x = blockIdx.y ? xb : xa;
    __half* o16 = blockIdx.y ? ob : oa;
    const float* xr = x + (size_t)warp * CDIM;
    float v[12];
    float s = 0.f;
    #pragma unroll
    for (int i = 0; i < 12; i++) { v[i] = xr[lane + i * 32]; s += v[i]; }
    s = warp_sum(s);
    float mu = s * (1.f / 384.f);
    float sq = 0.f;
    #pragma unroll
    for (int i = 0; i < 12; i++) { float dv = v[i] - mu; sq += dv * dv; }
    sq = warp_sum(sq);
    float rstd = rsqrtf(sq * (1.f / 384.f) + 1e-5f);
    size_t ro = (size_t)window_row(warp) * CDIM;
    #pragma unroll
    for (int i = 0; i < 12; i++) {
        int c = lane + i * 32;
        float o = (v[i] - mu) * rstd * g[c] + b[c];
        o16[ro + c] = __float2half(o);
    }
}

// ---------------------------------------------------------------------------
// residual-add (window_reverse) + LN2 -> x2 fp32, hn fp16
// ---------------------------------------------------------------------------
__global__ void __launch_bounds__(256) resln_kernel(
    const float* __restrict__ x, const float* __restrict__ aw,
    const float* __restrict__ g, const float* __restrict__ b,
    float* __restrict__ x2, __half* __restrict__ hn)
{
    int warp = (blockIdx.x * blockDim.x + threadIdx.x) >> 5;
    int lane = threadIdx.x & 31;
    if (warp >= BTROWS) return;
    const float* xr = x  + (size_t)warp * CDIM;
    const float* ar = aw + (size_t)window_row(warp) * CDIM;
    float v[12];
    float s = 0.f;
    #pragma unroll
    for (int i = 0; i < 12; i++) {
        int c = lane + i * 32;
        v[i] = xr[c] + ar[c];
        s += v[i];
    }
    s = warp_sum(s);
    float mu = s * (1.f / 384.f);
    float sq = 0.f;
    #pragma unroll
    for (int i = 0; i < 12; i++) { float dv = v[i] - mu; sq += dv * dv; }
    sq = warp_sum(sq);
    float rstd = rsqrtf(sq * (1.f / 384.f) + 1e-5f);
    size_t ro = (size_t)warp * CDIM;
    #pragma unroll
    for (int i = 0; i < 12; i++) {
        int c = lane + i * 32;
        x2[ro + c] = v[i];
        float o = (v[i] - mu) * rstd * g[c] + b[c];
        hn[ro + c] = __float2half(o);
    }
}

// ---------------------------------------------------------------------------
// mma.sync GEMM body (single fp16 pass), BK=64, 3-stage pipeline.
// SW128 swizzle: 128B rows, cs = ck ^ (row & 7).
// ---------------------------------------------------------------------------
#define GSTAGE 32768
#define GSMEM_BYTES (3*GSTAGE)

template <int EPI>
__device__ __forceinline__ void gemm_body(
    const __half* __restrict__ A, const __half* __restrict__ Bh,
    const float* __restrict__ bias, const float* __restrict__ res,
    float* __restrict__ C, __half* __restrict__ C16,
    int N, int K, int bm, int bn, char* smem)
{
    const uint32_t sbase = smem_u32(smem);
    const int tid  = threadIdx.x;
    const int lane = tid & 31;
    const int wid  = tid >> 5;
    const int wm   = wid & 1;
    const int wn   = wid >> 1;

    float acc[4][4][4];
    #pragma unroll
    for (int i = 0; i < 4; i++)
        #pragma unroll
        for (int j = 0; j < 4; j++)
            #pragma unroll
            for (int q = 0; q < 4; q++) acc[i][j][q] = 0.f;

    // stage: A tile 128x64 fp16 (16KB) + B tile 128x64 fp16 (16KB)
    #define LOAD_STAGE(stage, k0) do {                                        \
        uint32_t sb_ = sbase + (uint32_t)(stage) * GSTAGE;                    \
        const __half* bases_[2] = {A, Bh};                                    \
        _Pragma("unroll")                                                     \
        for (int sub_ = 0; sub_ < 2; sub_++) {                                \
            const __half* bp_ = bases_[sub_];                                 \
            int ro_ = (sub_ == 0) ? bm : bn;                                  \
            _Pragma("unroll")                                                 \
            for (int jj_ = 0; jj_ < 4; jj_++) {                               \
                int cid_ = tid + 256 * jj_;      /* 0..1023 */                \
                int row_ = cid_ >> 3, ck_ = cid_ & 7;                         \
                int cs_ = ck_ ^ (row_ & 7);                                   \
                const void* src_ = bp_ + (size_t)(ro_ + row_) * K + (k0) + ck_ * 8; \
                cp_async16(sb_ + (uint32_t)(sub_ << 14)                       \
                           + (uint32_t)(row_ * 128 + cs_ * 16), src_);        \
            }                                                                 \
        }                                                                     \
    } while (0)

    const int NC = K >> 6;
    LOAD_STAGE(0, 0);
    asm volatile("cp.async.commit_group;" ::: "memory");
    LOAD_STAGE(1, 64);
    asm volatile("cp.async.commit_group;" ::: "memory");

    const int arow = wm * 64 + (lane & 15);
    const int asel = lane >> 4;
    const int brow = wn * 32 + ((lane >> 4) << 3) + (lane & 7);
    const int bsel = (lane >> 3) & 1;

    int scur = 0, sld = 2;
    for (int c = 0; c < NC; c++) {
        if (c + 1 < NC) {
            asm volatile("cp.async.wait_group 1;" ::: "memory");
        } else {
            asm volatile("cp.async.wait_group 0;" ::: "memory");
        }
        __syncthreads();
        if (c + 2 < NC) {
            LOAD_STAGE(sld, (c + 2) << 6);
            asm volatile("cp.async.commit_group;" ::: "memory");
            sld = (sld == 2) ? 0 : sld + 1;
        }

        const uint32_t sb = sbase + (uint32_t)scur * GSTAGE;
        scur = (scur == 2) ? 0 : scur + 1;
        #pragma unroll
        for (int kk = 0; kk < 4; kk++) {
            uint32_t a[4][4], bh[2][4];
            #pragma unroll
            for (int mt = 0; mt < 4; mt++) {
                int row = arow + mt * 16;
                int ck  = kk * 2 + asel;
                uint32_t off = (uint32_t)(row * 128 + ((ck ^ (row & 7)) << 4));
                ldm4(a[mt], sb + off);
            }
            #pragma unroll
            for (int bt = 0; bt < 2; bt++) {
                int row = brow + bt * 16;
                int ck  = kk * 2 + bsel;
                uint32_t off = (uint32_t)(row * 128 + ((ck ^ (row & 7)) << 4));
                ldm4(bh[bt], sb + 16384u + off);
            }
            #pragma unroll
            for (int mt = 0; mt < 4; mt++) {
                #pragma unroll
                for (int nt = 0; nt < 4; nt++) {
                    const uint32_t* bhf = &bh[nt >> 1][(nt & 1) * 2];
                    mma16816(acc[mt][nt], a[mt], bhf);
                }
            }
        }
    }

    // ---- epilogue ----
    const int gr = lane >> 2;
    const int nc0 = (lane & 3) * 2;
    #pragma unroll
    for (int mt = 0; mt < 4; mt++) {
        #pragma unroll
        for (int nt = 0; nt < 4; nt++) {
            int col = bn + wn * 32 + nt * 8 + nc0;
            float bs0 = bias[col], bs1 = bias[col + 1];
            #pragma unroll
            for (int half = 0; half < 2; half++) {
                int row = bm + wm * 64 + mt * 16 + gr + half * 8;
                float v0 = acc[mt][nt][half * 2 + 0] + bs0;
                float v1 = acc[mt][nt][half * 2 + 1] + bs1;
                size_t off = (size_t)row * N + col;
                if (EPI == 1 || EPI == 3) {
                    if (EPI == 1) {
                        v0 = 0.5f * v0 * (1.f + erff(v0 * 0.70710678118654752f));
                        v1 = 0.5f * v1 * (1.f + erff(v1 * 0.70710678118654752f));
                    }
                    __half2 p = __halves2half2(__float2half(v0), __float2half(v1));
                    *(uint32_t*)(C16 + off) = *(uint32_t*)&p;
                } else {
                    if (EPI == 2) { v0 += res[off]; v1 += res[off + 1]; }
                    float2 o; o.x = v0; o.y = v1;
                    *(float2*)(C + off) = o;
                }
            }
        }
    }
    #undef LOAD_STAGE
}

template <int EPI>
__global__ void __launch_bounds__(256, 2) mma_gemm(
    const __half* __restrict__ A, const __half* __restrict__ Bh,
    const float* __restrict__ bias, const float* __restrict__ res,
    float* __restrict__ C, __half* __restrict__ C16, int N, int K)
{
    extern __shared__ char smem[];
    gemm_body<EPI>(A, Bh, bias, res, C, C16, N, K,
                   blockIdx.y * 128, blockIdx.x * 128, smem);
}

// fused kvg + q GEMM: blockIdx.x < 9 -> kvg tile, else q tile
__global__ void __launch_bounds__(256, 2) mma_gemm_qkv(
    const __half* __restrict__ xw, const __half* __restrict__ yw,
    const __half* __restrict__ wq, const float* __restrict__ bq,
    __half* __restrict__ kvg16, __half* __restrict__ qb16)
{
    extern __shared__ char smem[];
    if (blockIdx.x < 9) {
        gemm_body<3>(xw, wq + 384*384, bq + 384, nullptr, nullptr, kvg16,
                     KVGC, 384, blockIdx.y * 128, blockIdx.x * 128, smem);
    } else {
        gemm_body<3>(yw, wq, bq, nullptr, nullptr, qb16,
                     CDIM, 384, blockIdx.y * 128, (blockIdx.x - 9) * 128, smem);
    }
}

// ---------------------------------------------------------------------------
// Pola linear attention, one block per (window, head). 256 threads.
// 128-token chunks; d-quad loaders; float4 ksum partials (aliased into buf);
// z folded. Natural register allocation (3 CTAs/SM).
// Dynamic smem (floats): sc[32] pw[32] km2[2][64] buf[128][68] vS[128][36]
// ---------------------------------------------------------------------------
#define ATTN_SMEM ((32 + 32 + 128 + 128*68 + 128*36) * 4)

__global__ void __launch_bounds__(256) attn_kernel(
    const __half* __restrict__ kvg, const __half* __restrict__ qb,
    const float* __restrict__ pos_enc, const float* __restrict__ scale_p,
    const float* __restrict__ power_p, __half* __restrict__ xo)
{
    extern __shared__ float asmem[];
    float* sc_s  = asmem;            // [32]
    float* pw_s  = asmem + 32;       // [32]
    float* km2_s = asmem + 64;       // [2][64]
    float (*buf)[68] = (float(*)[68])(asmem + 192);
    float (*vS)[36]  = (float(*)[36])(asmem + 192 + 128*68);
    float* ks16  = asmem + 192;      // [16][64] alias of buf (free between phases)

    const int wg = blockIdx.x;   // 0..63
    const int h  = blockIdx.y;   // 0..11
    const int tid = threadIdx.x;

    if (tid < 32) {
        float sp = scale_p[h * 32 + tid];
        sc_s[tid] = 1.f / log1pf(expf(sp));          // 1/softplus
        float pp = power_p[h * 32 + tid];
        pw_s[tid] = 1.f + 4.f / (1.f + expf(-pp));   // 1 + ALPHA*sigmoid
    }
    __syncthreads();

    const int nh = tid >> 7;
    const int tt = tid & 127;
    const int fq = (tt >> 3) << 2;
    const int dq = (tt & 7) << 2;
    const int kfg = (tid & 15) << 2;  // ksum feature quad base
    const int krg = tid >> 4;         // ksum row group (0..15), 8 rows each

    float acc[4][4];
    #pragma unroll
    for (int i = 0; i < 4; i++)
        #pragma unroll
        for (int j = 0; j < 4; j++) acc[i][j] = 0.f;
    float ks0 = 0.f, ks1 = 0.f, ks2 = 0.f, ks3 = 0.f;

    // -------- phase A: kc features (d-quad loader), kv = kc^T v, ksum -------
    for (int c0 = 0; c0 < WN; c0 += 128) {
        #pragma unroll
        for (int i = 0; i < 4; i++) {
            int idx = tid + 256 * i;      // 0..1023
            int nl = idx >> 3;            // 0..127
            int d0 = (idx & 7) << 2;      // 0,4,..,28
            int row = wg * WN + c0 + nl;
            uint2 ku = *(const uint2*)&kvg[(size_t)row * KVGC + h * 32 + d0];
            float2 ka = __half22float2(*(__half2*)&ku.x);
            float2 kb = __half22float2(*(__half2*)&ku.y);
            float4 pe = *(const float4*)&pos_enc[(c0 + nl) * CDIM + h * 32 + d0];
            float kv0 = (ka.x + pe.x) * sc_s[d0];
            float kv1 = (ka.y + pe.y) * sc_s[d0 + 1];
            float kv2 = (kb.x + pe.z) * sc_s[d0 + 2];
            float kv3 = (kb.y + pe.w) * sc_s[d0 + 3];
            float r0 = fast_pow(fabsf(kv0), pw_s[d0]);
            float r1 = fast_pow(fabsf(kv1), pw_s[d0 + 1]);
            float r2 = fast_pow(fabsf(kv2), pw_s[d0 + 2]);
            float r3 = fast_pow(fabsf(kv3), pw_s[d0 + 3]);
            float4 pv, nv;
            pv.x = kv0 > 0.f ? r0 : 0.f; nv.x = kv0 < 0.f ? r0 : 0.f;
            pv.y = kv1 > 0.f ? r1 : 0.f; nv.y = kv1 < 0.f ? r1 : 0.f;
            pv.z = kv2 > 0.f ? r2 : 0.f; nv.z = kv2 < 0.f ? r2 : 0.f;
            pv.w = kv3 > 0.f ? r3 : 0.f; nv.w = kv3 < 0.f ? r3 : 0.f;
            *(float4*)&buf[nl][d0]      = pv;
            *(float4*)&buf[nl][d0 + 32] = nv;
            uint2 vu = *(const uint2*)&kvg[(size_t)row * KVGC + 384 + h * 32 + d0];
            float2 va = __half22float2(*(__half2*)&vu.x);
            float2 vb = __half22float2(*(__half2*)&vu.y);
            float4 vf; vf.x = va.x; vf.y = va.y; vf.z = vb.x; vf.w = vb.y;
            *(float4*)&vS[nl][d0] = vf;
        }
        __syncthreads();
        #pragma unroll 4
        for (int n = 0; n < 64; n++) {
            int nn = (nh << 6) + n;
            float4 kq = *(const float4*)&buf[nn][fq];
            float4 v4 = *(const float4*)&vS[nn][dq];
            acc[0][0] += kq.x * v4.x; acc[0][1] += kq.x * v4.y;
            acc[0][2] += kq.x * v4.z; acc[0][3] += kq.x * v4.w;
            acc[1][0] += kq.y * v4.x; acc[1][1] += kq.y * v4.y;
            acc[1][2] += kq.y * v4.z; acc[1][3] += kq.y * v4.w;
            acc[2][0] += kq.z * v4.x; acc[2][1] += kq.z * v4.y;
            acc[2][2] += kq.z * v4.z; acc[2][3] += kq.z * v4.w;
            acc[3][0] += kq.w * v4.x; acc[3][1] += kq.w * v4.y;
            acc[3][2] += kq.w * v4.z; acc[3][3] += kq.w * v4.w;
        }
        // ksum partial: 8 rows x feature-quad per thread, float4 loads
        #pragma unroll
        for (int n = 0; n < 8; n++) {
            float4 kq = *(const float4*)&buf[krg * 8 + n][kfg];
            ks0 += kq.x; ks1 += kq.y; ks2 += kq.z; ks3 += kq.w;
        }
        __syncthreads();
    }

    // -------- merge n-halves + ksum partials, write M and km vectors --------
    float4 ksq; ksq.x = ks0; ksq.y = ks1; ksq.z = ks2; ksq.w = ks3;
    *(float4*)&ks16[krg * 64 + kfg] = ksq;
    if (nh == 1) {
        #pragma unroll
        for (int i = 0; i < 4; i++)
            #pragma unroll
            for (int j = 0; j < 4; j++)
                vS[fq + i][dq + j] = acc[i][j];
    }
    __syncthreads();
    float mreg[4][4];
    if (nh == 0) {
        const float sN2 = 1.f / 512.f;
        #pragma unroll
        for (int i = 0; i < 4; i++)
            #pragma unroll
            for (int j = 0; j < 4; j++)
                mreg[i][j] = (acc[i][j] + vS[fq + i][dq + j]) * sN2;
    }
    if (tid < 64) {
        float km = 0.f;
        #pragma unroll
        for (int r = 0; r < 16; r++) km += ks16[r * 64 + tid];
        km *= (1.f / 512.f);
        km2_s[tid] = km;
        km2_s[64 + ((tid + 32) & 63)] = km;
    }
    __syncthreads();
    if (nh == 0) {
        #pragma unroll
        for (int i = 0; i < 4; i++) {
            int fr = (dq < 16) ? (fq + i) : ((fq + i + 32) & 63);
            #pragma unroll
            for (int j = 0; j < 4; j++)
                vS[fr][dq + j] = mreg[i][j];
        }
    }
    __syncthreads();

    // -------- phase C: q features (d-quad loader) + O = qf @ M + z, write ---
    const int n0 = (tid >> 3) << 2;   // 0,4,..,124
    const int vc = (tid & 7) << 2;    // 0,4,..,28
    const int zi = (vc >= 16) ? 1 : 0;
    const float* kmz = km2_s + zi * 64;
    for (int c0 = 0; c0 < WN; c0 += 128) {
        #pragma unroll
        for (int i = 0; i < 4; i++) {
            int idx = tid + 256 * i;
            int nl = idx >> 3;
            int d0 = (idx & 7) << 2;
            int row = wg * WN + c0 + nl;
            uint2 qu = *(const uint2*)&qb[(size_t)row * CDIM + h * 32 + d0];
            float2 qa = __half22float2(*(__half2*)&qu.x);
            float2 qc = __half22float2(*(__half2*)&qu.y);
            float qv0 = qa.x * sc_s[d0];
            float qv1 = qa.y * sc_s[d0 + 1];
            float qv2 = qc.x * sc_s[d0 + 2];
            float qv3 = qc.y * sc_s[d0 + 3];
            float r0 = fast_pow(fabsf(qv0), pw_s[d0]);
            float r1 = fast_pow(fabsf(qv1), pw_s[d0 + 1]);
            float r2 = fast_pow(fabsf(qv2), pw_s[d0 + 2]);
            float r3 = fast_pow(fabsf(qv3), pw_s[d0 + 3]);
            float4 pv, nv;
            pv.x = qv0 > 0.f ? r0 : 0.f; nv.x = qv0 < 0.f ? r0 : 0.f;
            pv.y = qv1 > 0.f ? r1 : 0.f; nv.y = qv1 < 0.f ? r1 : 0.f;
            pv.z = qv2 > 0.f ? r2 : 0.f; nv.z = qv2 < 0.f ? r2 : 0.f;
            pv.w = qv3 > 0.f ? r3 : 0.f; nv.w = qv3 < 0.f ? r3 : 0.f;
            *(float4*)&buf[nl][d0]      = pv;
            *(float4*)&buf[nl][d0 + 32] = nv;
        }
        __syncthreads();

        float a[4][4];
        float z[4];
        #pragma unroll
        for (int t = 0; t < 4; t++) {
            z[t] = 1e-6f;
            #pragma unroll
            for (int j = 0; j < 4; j++) a[t][j] = 0.f;
        }
        #pragma unroll 2
        for (int f = 0; f < 64; f += 4) {
            float4 m0 = *(const float4*)&vS[f + 0][vc];
            float4 m1 = *(const float4*)&vS[f + 1][vc];
            float4 m2 = *(const float4*)&vS[f + 2][vc];
            float4 m3 = *(const float4*)&vS[f + 3][vc];
            float4 kv = *(const float4*)&kmz[f];
            #pragma unroll
            for (int t = 0; t < 4; t++) {
                float4 q = *(const float4*)&buf[n0 + t][f];
                a[t][0] += q.x * m0.x + q.y * m1.x + q.z * m2.x + q.w * m3.x;
                a[t][1] += q.x * m0.y + q.y * m1.y + q.z * m2.y + q.w * m3.y;
                a[t][2] += q.x * m0.z + q.y * m1.z + q.z * m2.z + q.w * m3.z;
                a[t][3] += q.x * m0.w + q.y * m1.w + q.z * m2.w + q.w * m3.w;
                z[t]    += q.x * kv.x + q.y * kv.y + q.z * kv.z + q.w * kv.w;
            }
        }

        size_t base0 = (size_t)(wg * WN + c0 + n0) * CDIM + h * 32 + vc;
        #pragma unroll
        for (int t = 0; t < 4; t++) {
            float rz = 1.f / z[t];
            __half2 p0 = __halves2half2(__float2half(a[t][0] * rz),
                                        __float2half(a[t][1] * rz));
            __half2 p1 = __halves2half2(__float2half(a[t][2] * rz),
                                        __float2half(a[t][3] * rz));
            uint2 o; o.x = *(uint32_t*)&p0; o.y = *(uint32_t*)&p1;
            *(uint2*)&xo[base0 + (size_t)t * CDIM] = o;
        }
        __syncthreads();
    }
}

// ---------------------------------------------------------------------------
// Depthwise 5^3 conv + (xo + vv) * g, in place on fp16 xo plane.
// Round-9 form: scalar fp32 smem, thread owns one d; 16-output register tile.
// ---------------------------------------------------------------------------
#define CONV_SMEM ((512*32 + 125*32) * 4)

__global__ void __launch_bounds__(256) dwconv_kernel(
    const __half* __restrict__ kvg, const float* __restrict__ dwc_w,
    const float* __restrict__ dwc_b, __half* __restrict__ xo16)
{
    extern __shared__ float sm[];
    float* v_s = sm;               // [512][32] fp32
    float* w_s = sm + 512 * 32;    // [125][32] fp32
    const int bh = blockIdx.x;
    const int b_ = bh / NHEADS, h = bh % NHEADS;
    const int tid = threadIdx.x;

    for (int i = tid; i < 512 * 32; i += 256) {
        int n = i >> 5, d = i & 31;
        v_s[i] = __half2float(kvg[(size_t)(b_ * WN + n) * KVGC + 384 + h * 32 + d]);
    }
    for (int i = tid; i < 125 * 32; i += 256) w_s[i] = dwc_w[i];
    __syncthreads();

    const int d  = tid & 31;
    const int lo = tid >> 5;
    const float bval = dwc_b[d];
    const size_t base = (size_t)b_ * (WN * CDIM) + (size_t)h * (WN * HD);

    for (int jg = 0; jg < 4; jg++) {
        float acc[16];
        #pragma unroll
        for (int jj = 0; jj < 16; jj++) acc[jj] = bval;
        for (int kd = 0; kd < 5; kd++) {
            for (int kh = 0; kh < 5; kh++) {
                for (int kw = 0; kw < 5; kw++) {
                    int li = lo + kw - 2;
                    if (li < 0 || li > 7) continue;
                    float w = w_s[((kd * 5 + kh) * 5 + kw) * 32 + d];
                    #pragma unroll
                    for (int jj = 0; jj < 16; jj++) {
                        int j = jg * 16 + jj;
                        int hi = (j >> 3) + kd - 2;
                        int wi = (j & 7) + kh - 2;
                        if (hi < 0 || hi > 7 || wi < 0 || wi > 7) continue;
                        acc[jj] += v_s[((hi * 8 + wi) * 8 + li) * 32 + d] * w;
                    }
                }
            }
        }
        #pragma unroll
        for (int jj = 0; jj < 16; jj++) {
            int j = jg * 16 + jj;
            size_t flat = base + (size_t)(lo + 8 * j) * 32 + d;
            size_t grow = flat / CDIM;
            int    gcol = (int)(flat % CDIM);
            float g = __half2float(kvg[grow * KVGC + 768 + gcol]);
            float val = (__half2float(xo16[flat]) + acc[jj]) * g;
            xo16[flat] = __float2half(val);
        }
    }
}

// ---------------------------------------------------------------------------
// kernel_launch
// ---------------------------------------------------------------------------
extern "C" void kernel_launch(void* const* d_in, const int* in_sizes, int n_in,
                              void* d_out, int out_size)
{
    const float* x       = (const float*)d_in[0];
    const float* y       = (const float*)d_in[1];
    const float* w_qkvg  = (const float*)d_in[2];
    const float* b_qkvg  = (const float*)d_in[3];
    const float* w_proj  = (const float*)d_in[4];
    const float* b_proj  = (const float*)d_in[5];
    const float* dwc_w   = (const float*)d_in[6];
    const float* dwc_b   = (const float*)d_in[7];
    const float* power_p = (const float*)d_in[8];
    const float* scale_p = (const float*)d_in[9];
    const float* pos_enc = (const float*)d_in[10];
    const float* g1      = (const float*)d_in[11];
    const float* b1      = (const float*)d_in[12];
    const float* g2      = (const float*)d_in[13];
    const float* b2      = (const float*)d_in[14];
    const float* w_fc1   = (const float*)d_in[15];
    const float* b_fc1   = (const float*)d_in[16];
    const float* w_fc2   = (const float*)d_in[17];
    const float* b_fc2   = (const float*)d_in[18];
    float* out = (float*)d_out;

    __half *p_xw16, *p_yw16, *p_hn16, *p_xo16, *p_h116, *p_kvg16, *p_qb16;
    __half *p_wqh, *p_wph, *p_w1h, *p_w2h;
    float *p_aw, *p_x2;
    cudaGetSymbolAddress((void**)&p_xw16, d_xw16);
    cudaGetSymbolAddress((void**)&p_yw16, d_yw16);
    cudaGetSymbolAddress((void**)&p_hn16, d_hn16);
    cudaGetSymbolAddress((void**)&p_xo16, d_xo16);
    cudaGetSymbolAddress((void**)&p_h116, d_h116);
    cudaGetSymbolAddress((void**)&p_kvg16, d_kvg16);
    cudaGetSymbolAddress((void**)&p_qb16, d_qb16);
    cudaGetSymbolAddress((void**)&p_wqh, d_wqh);
    cudaGetSymbolAddress((void**)&p_wph, d_wph);
    cudaGetSymbolAddress((void**)&p_w1h, d_w1h);
    cudaGetSymbolAddress((void**)&p_w2h, d_w2h);
    cudaGetSymbolAddress((void**)&p_aw,  d_aw);
    cudaGetSymbolAddress((void**)&p_x2,  d_x2);

    cudaFuncSetAttribute(dwconv_kernel,
                         cudaFuncAttributeMaxDynamicSharedMemorySize, CONV_SMEM);
    cudaFuncSetAttribute(attn_kernel,
                         cudaFuncAttributeMaxDynamicSharedMemorySize, ATTN_SMEM);
    cudaFuncSetAttribute(mma_gemm<0>,
                         cudaFuncAttributeMaxDynamicSharedMemorySize, GSMEM_BYTES);
    cudaFuncSetAttribute(mma_gemm<1>,
                         cudaFuncAttributeMaxDynamicSharedMemorySize, GSMEM_BYTES);
    cudaFuncSetAttribute(mma_gemm<2>,
                         cudaFuncAttributeMaxDynamicSharedMemorySize, GSMEM_BYTES);
    cudaFuncSetAttribute(mma_gemm_qkv,
                         cudaFuncAttributeMaxDynamicSharedMemorySize, GSMEM_BYTES);

    // 0) weight -> fp16, single launch
    {
        int n0 = 1536*384/4, n1 = 384*384/4, n2 = 1536*384/4, n3 = 384*1536/4;
        int tot = n0 + n1 + n2 + n3;
        cvt_all_kernel<<<(tot + 255)/256, 256>>>(
            (const float4*)w_qkvg, (uint2*)p_wqh, n0,
            (const float4*)w_proj, (uint2*)p_wph, n1,
            (const float4*)w_fc1,  (uint2*)p_w1h, n2,
            (const float4*)w_fc2,  (uint2*)p_w2h, n3);
    }

    // 1) LN + window partition (x and y in one launch) -> fp16
    ln_win_kernel<<<dim3(BTROWS / 8, 2), 256>>>(x, y, g1, b1, p_xw16, p_yw16);

    // 2+3) fused kvg + q GEMM (single pass) -> fp16
    mma_gemm_qkv<<<dim3(12, BTROWS/128), 256, GSMEM_BYTES>>>(
        p_xw16, p_yw16, p_wqh, b_qkvg, p_kvg16, p_qb16);

    // 4) attention -> xo16
    attn_kernel<<<dim3(NWIN, NHEADS), 256, ATTN_SMEM>>>(
        p_kvg16, p_qb16, pos_enc, scale_p, power_p, p_xo16);

    // 5) depthwise conv + gating, in place on xo16
    dwconv_kernel<<<NWIN * NHEADS, 256, CONV_SMEM>>>(p_kvg16, dwc_w, dwc_b,
                                                     p_xo16);

    // 6) aw = xo @ w_proj^T + b_proj -> fp32 (single pass)
    mma_gemm<0><<<dim3(CDIM/128, BTROWS/128), 256, GSMEM_BYTES>>>(
        p_xo16, p_wph, b_proj, nullptr, p_aw, nullptr, CDIM, 384);

    // 7) x2 = x + window_reverse(aw); hn = LN2(x2) -> fp16
    resln_kernel<<<BTROWS / 8, 256>>>(x, p_aw, g2, b2, p_x2, p_hn16);

    // 8) h1 = gelu(hn @ w_fc1^T + b_fc1) -> fp16 (single pass, N=1536)
    mma_gemm<1><<<dim3(HIDDEN/128, BTROWS/128), 256, GSMEM_BYTES>>>(
        p_hn16, p_w1h, b_fc1, nullptr, nullptr, p_h116, HIDDEN, 384);

    // 9) out = x2 + h1 @ w_fc2^T + b_fc2 (single pass, K=1536)
    mma_gemm<2><<<dim3(CDIM/128, BTROWS/128), 256, GSMEM_BYTES>>>(
        p_h116, p_w2h, b_fc2, p_x2, out, nullptr, CDIM, 1536);
}